// round 5
// baseline (speedup 1.0000x reference)
#include <cuda_runtime.h>
#include <cuda_bf16.h>

#define N        1024
#define ED       256
#define HD       128
#define TSP      64      // pair-tile size

// ---------------- scratch (no allocation allowed) ----------------
__device__ float g_WfA[ED * 2 * HD];     // fused-weight partial, k 0..63
__device__ float g_WfB[ED * 2 * HD];     // fused-weight partial, k 64..127
__device__ float g_biasf[2 * HD];        // fused biases (q half includes b1)
__device__ float g_qkA[N * 2 * HD];      // qk partial, e 0..127
__device__ float g_qkB[N * 2 * HD];      // qk partial, e 128..255

// ---------------- kernel B: fused weights + ctx/bias (merged) -------------
// blockIdx.z<2: GEMM Wf = [Wq@W1top | Wk@W1bot], 256x256x128 split-K=2.
// blockIdx.z==2 && x==0 && y==0: ctx = relu(emb@Wc+bc); fused biases.
__global__ void __launch_bounds__(128)
wfuse_kernel(const float* __restrict__ Wq,
             const float* __restrict__ Wk,
             const float* __restrict__ W1,
             const float* __restrict__ emb,
             const float* __restrict__ Wc,
             const float* __restrict__ bc,
             const float* __restrict__ bq,
             const float* __restrict__ bk,
             const float* __restrict__ b1) {
    __shared__ float AsT[64 * 65];   // [k][e], scalar-store transpose, stride 65
    __shared__ float Bs[64][32];     // [k][n]
    int t = threadIdx.x;

    if (blockIdx.z == 2) {
        if (blockIdx.x != 0 || blockIdx.y != 0) return;
        // ---- ctx + fused biases with 128 threads ----
        float* semb = AsT;                 // reuse smem: 256 floats
        float* sq   = AsT + 256;           // 128
        float* sk   = AsT + 384;           // 128
        semb[t] = emb[t];
        semb[t + 128] = emb[t + 128];
        __syncthreads();
        {
            float s = bc[t];
            #pragma unroll 8
            for (int k = 0; k < ED; k++)
                s = fmaf(semb[k], Wc[k * HD + t], s);
            float ctx = fmaxf(s, 0.f);
            sq[t] = bq[t] + ctx;
            sk[t] = bk[t] + ctx;
        }
        __syncthreads();
        {
            float s0 = b1[t];
            float s1 = 0.f;
            #pragma unroll 8
            for (int k = 0; k < HD; k++) {
                s0 = fmaf(sq[k], W1[k * HD + t], s0);
                s1 = fmaf(sk[k], W1[(HD + k) * HD + t], s1);
            }
            g_biasf[t] = s0;
            g_biasf[HD + t] = s1;
        }
        return;
    }

    int nb = blockIdx.x * 32;
    int e0 = blockIdx.y * 64;
    int k0 = blockIdx.z * 64;
    int half = nb >> 7;              // 0 -> q-cols (Wq/W1top), 1 -> k-cols
    int ncol = nb & 127;
    const float* A = half ? Wk : Wq;
    int tx = t & 7, ty = t >> 3;

    #pragma unroll
    for (int l = 0; l < 8; l++) {              // A: 64(e) x 64(k), transposed
        int idx = l * 128 + t;
        int e16 = idx & 15, i = idx >> 4;
        float4 v = *(const float4*)&A[(e0 + i) * HD + k0 + 4 * e16];
        AsT[(4 * e16 + 0) * 65 + i] = v.x;
        AsT[(4 * e16 + 1) * 65 + i] = v.y;
        AsT[(4 * e16 + 2) * 65 + i] = v.z;
        AsT[(4 * e16 + 3) * 65 + i] = v.w;
    }
    #pragma unroll
    for (int l = 0; l < 4; l++) {              // B: 64x32 floats
        int idx = l * 128 + t;
        int c4 = idx & 7, row = idx >> 3;
        *(float4*)&Bs[row][4 * c4] =
            *(const float4*)&W1[(half * HD + k0 + row) * HD + ncol + 4 * c4];
    }
    __syncthreads();

    float acc[4][4] = {};
    #pragma unroll 4
    for (int k = 0; k < 64; k++) {
        float a0 = AsT[k * 65 + 4 * ty + 0];
        float a1 = AsT[k * 65 + 4 * ty + 1];
        float a2 = AsT[k * 65 + 4 * ty + 2];
        float a3 = AsT[k * 65 + 4 * ty + 3];
        float4 b = *(const float4*)&Bs[k][4 * tx];
        acc[0][0] = fmaf(a0, b.x, acc[0][0]); acc[0][1] = fmaf(a0, b.y, acc[0][1]);
        acc[0][2] = fmaf(a0, b.z, acc[0][2]); acc[0][3] = fmaf(a0, b.w, acc[0][3]);
        acc[1][0] = fmaf(a1, b.x, acc[1][0]); acc[1][1] = fmaf(a1, b.y, acc[1][1]);
        acc[1][2] = fmaf(a1, b.z, acc[1][2]); acc[1][3] = fmaf(a1, b.w, acc[1][3]);
        acc[2][0] = fmaf(a2, b.x, acc[2][0]); acc[2][1] = fmaf(a2, b.y, acc[2][1]);
        acc[2][2] = fmaf(a2, b.z, acc[2][2]); acc[2][3] = fmaf(a2, b.w, acc[2][3]);
        acc[3][0] = fmaf(a3, b.x, acc[3][0]); acc[3][1] = fmaf(a3, b.y, acc[3][1]);
        acc[3][2] = fmaf(a3, b.z, acc[3][2]); acc[3][3] = fmaf(a3, b.w, acc[3][3]);
    }
    float* outp = blockIdx.z ? g_WfB : g_WfA;
    #pragma unroll
    for (int r = 0; r < 4; r++)
        *(float4*)&outp[(e0 + 4 * ty + r) * 256 + nb + 4 * tx] =
            make_float4(acc[r][0], acc[r][1], acc[r][2], acc[r][3]);
}

// ---------------- kernel C: GEMM qk = prev @ Wf (split-K=2) ----------------
__global__ void __launch_bounds__(128)
gemm_kernel(const float* __restrict__ prev) {
    extern __shared__ float sm[];
    float* AsT = sm;                 // [128(k)][65(m)] scalar-store transpose
    float* Bs  = sm + 128 * 65;      // [128][32]
    int nb = blockIdx.x * 32;
    int i0 = blockIdx.y * 64;
    int k0 = blockIdx.z * 128;
    int t = threadIdx.x, tx = t & 7, ty = t >> 3;

    #pragma unroll
    for (int l = 0; l < 16; l++) {             // A: 64(m) x 128(k), transposed
        int idx = l * 128 + t;
        int e4 = idx & 31, i = idx >> 5;
        float4 v = *(const float4*)&prev[(i0 + i) * ED + k0 + 4 * e4];
        AsT[(4 * e4 + 0) * 65 + i] = v.x;
        AsT[(4 * e4 + 1) * 65 + i] = v.y;
        AsT[(4 * e4 + 2) * 65 + i] = v.z;
        AsT[(4 * e4 + 3) * 65 + i] = v.w;
    }
    #pragma unroll
    for (int l = 0; l < 8; l++) {              // B: 128x32, sum wfuse partials
        int idx = l * 128 + t;
        int c4 = idx & 7, row = idx >> 3;
        int off = (k0 + row) * 256 + nb + 4 * c4;
        float4 a = *(const float4*)&g_WfA[off];
        float4 b = *(const float4*)&g_WfB[off];
        *(float4*)&Bs[row * 32 + 4 * c4] =
            make_float4(a.x + b.x, a.y + b.y, a.z + b.z, a.w + b.w);
    }
    __syncthreads();

    float acc[4][4] = {};
    #pragma unroll 4
    for (int k = 0; k < 128; k++) {
        float a0 = AsT[k * 65 + 4 * ty + 0];
        float a1 = AsT[k * 65 + 4 * ty + 1];
        float a2 = AsT[k * 65 + 4 * ty + 2];
        float a3 = AsT[k * 65 + 4 * ty + 3];
        float4 b = *(const float4*)&Bs[k * 32 + 4 * tx];
        acc[0][0] = fmaf(a0, b.x, acc[0][0]); acc[0][1] = fmaf(a0, b.y, acc[0][1]);
        acc[0][2] = fmaf(a0, b.z, acc[0][2]); acc[0][3] = fmaf(a0, b.w, acc[0][3]);
        acc[1][0] = fmaf(a1, b.x, acc[1][0]); acc[1][1] = fmaf(a1, b.y, acc[1][1]);
        acc[1][2] = fmaf(a1, b.z, acc[1][2]); acc[1][3] = fmaf(a1, b.w, acc[1][3]);
        acc[2][0] = fmaf(a2, b.x, acc[2][0]); acc[2][1] = fmaf(a2, b.y, acc[2][1]);
        acc[2][2] = fmaf(a2, b.z, acc[2][2]); acc[2][3] = fmaf(a2, b.w, acc[2][3]);
        acc[3][0] = fmaf(a3, b.x, acc[3][0]); acc[3][1] = fmaf(a3, b.y, acc[3][1]);
        acc[3][2] = fmaf(a3, b.z, acc[3][2]); acc[3][3] = fmaf(a3, b.w, acc[3][3]);
    }
    float* outp = blockIdx.z ? g_qkB : g_qkA;
    #pragma unroll
    for (int r = 0; r < 4; r++)
        *(float4*)&outp[(i0 + 4 * ty + r) * 256 + nb + 4 * tx] =
            make_float4(acc[r][0], acc[r][1], acc[r][2], acc[r][3]);
}

// ---------------- kernel D: pair scores, 512 threads, h-split --------------
#define PSTEP(ACC, QP, KP, WP)                                        \
    asm("{\n\t"                                                       \
        ".reg .b64 s; .reg .f32 lo, hi;\n\t"                          \
        "add.rn.f32x2 s, %1, %2;\n\t"                                 \
        "mov.b64 {lo, hi}, s;\n\t"                                    \
        "max.f32 lo, lo, 0f00000000;\n\t"                             \
        "max.f32 hi, hi, 0f00000000;\n\t"                             \
        "mov.b64 s, {lo, hi};\n\t"                                    \
        "fma.rn.f32x2 %0, s, %3, %0;\n\t"                             \
        "}" : "+l"(ACC) : "l"(QP), "l"(KP), "l"(WP))

__global__ void __launch_bounds__(512, 1)
pair_kernel(const float* __restrict__ W2,
            const float* __restrict__ b2,
            float* __restrict__ out) {
    extern __shared__ float sm[];
    float* qs  = sm;                   // [64][128] swizzled, bias folded
    float* ks  = sm + TSP * HD;        // [64][128] swizzled, bias folded
    float* w2s = sm + 2 * TSP * HD;    // [128]
    float* red = sm + 2 * TSP * HD + HD;  // [64][65] partial-sum scratch

    // decode 1D block id -> upper-triangular tile (it <= jt), 16x16 tiles
    int rem = blockIdx.x;
    int it = 0;
    #pragma unroll
    for (int r = 0; r < 16; r++) {
        int len = 16 - r;
        if (rem < len) { it = r; break; }
        rem -= len;
    }
    int jt = it + rem;

    int t = threadIdx.x;
    int ibase = it * TSP, jbase = jt * TSP;

    // load tiles: sum split-K partials + fold fused bias; XOR-swizzled rows
    {
        int h4 = t & 31;                       // fixed column group per thread
        float4 bq4 = *(const float4*)&g_biasf[4 * h4];
        float4 bk4 = *(const float4*)&g_biasf[HD + 4 * h4];
        #pragma unroll
        for (int l = 0; l < 4; l++) {
            int i = (t >> 5) + 16 * l;
            int qo = (ibase + i) * 256 + 4 * h4;
            int ko = (jbase + i) * 256 + HD + 4 * h4;
            float4 qa = *(const float4*)&g_qkA[qo];
            float4 qb = *(const float4*)&g_qkB[qo];
            float4 ka = *(const float4*)&g_qkA[ko];
            float4 kb = *(const float4*)&g_qkB[ko];
            float4 qv = make_float4(qa.x + qb.x + bq4.x, qa.y + qb.y + bq4.y,
                                    qa.z + qb.z + bq4.z, qa.w + qb.w + bq4.w);
            float4 kv = make_float4(ka.x + kb.x + bk4.x, ka.y + kb.y + bk4.y,
                                    ka.z + kb.z + bk4.z, ka.w + kb.w + bk4.w);
            int sw = 4 * (h4 ^ ((i >> 2) & 7));
            *(float4*)&qs[i * HD + sw] = qv;
            *(float4*)&ks[i * HD + sw] = kv;
        }
    }
    if (t < HD) w2s[t] = W2[t];
    __syncthreads();

    int hg = t >> 8;                // h-group: 0 -> h4 0..15, 1 -> h4 16..31
    int tt = t & 255;
    int tx = tt & 15, ty = tt >> 4;
    int i0 = ty * 4, j0 = tx * 4;
    int swq = ty & 7, swk = tx & 7;

    unsigned long long acc[4][4];
    #pragma unroll
    for (int a = 0; a < 4; a++)
        #pragma unroll
        for (int b = 0; b < 4; b++)
            acc[a][b] = 0ull;

    int h4beg = hg * 16;
    #pragma unroll 2
    for (int hh = 0; hh < 16; hh++) {
        int h4 = h4beg + hh;
        int hq = 4 * (h4 ^ swq);
        int hk = 4 * (h4 ^ swk);
        ulonglong2 q[4], k[4];
        #pragma unroll
        for (int a = 0; a < 4; a++)
            q[a] = *(const ulonglong2*)&qs[(i0 + a) * HD + hq];
        #pragma unroll
        for (int b = 0; b < 4; b++)
            k[b] = *(const ulonglong2*)&ks[(j0 + b) * HD + hk];
        ulonglong2 w = *(const ulonglong2*)&w2s[4 * h4];
        #pragma unroll
        for (int a = 0; a < 4; a++)
            #pragma unroll
            for (int b = 0; b < 4; b++) {
                PSTEP(acc[a][b], q[a].x, k[b].x, w.x);
                PSTEP(acc[a][b], q[a].y, k[b].y, w.y);
            }
    }

    // reduce packed halves -> scalar partials
    float s[4][4];
    #pragma unroll
    for (int a = 0; a < 4; a++)
        #pragma unroll
        for (int b = 0; b < 4; b++) {
            unsigned long long v = acc[a][b];
            s[a][b] = __int_as_float((unsigned)v) +
                      __int_as_float((unsigned)(v >> 32));
        }

    // h-high half deposits partials in smem scratch
    if (hg) {
        #pragma unroll
        for (int a = 0; a < 4; a++)
            #pragma unroll
            for (int b = 0; b < 4; b++)
                red[(i0 + a) * 65 + j0 + b] = s[a][b];
    }
    __syncthreads();

    if (!hg) {
        float bias = b2[0];
        #pragma unroll
        for (int a = 0; a < 4; a++) {
            int i = ibase + i0 + a;
            int rowoff = i * N - ((i * (i + 1)) >> 1) - i - 1;
            #pragma unroll
            for (int b = 0; b < 4; b++) {
                int j = jbase + j0 + b;
                if (i < j)
                    out[rowoff + j] =
                        s[a][b] + red[(i0 + a) * 65 + j0 + b] + bias;
            }
        }
    }
}

// ---------------- launch ----------------
extern "C" void kernel_launch(void* const* d_in, const int* in_sizes, int n_in,
                              void* d_out, int out_size) {
    const float* emb  = (const float*)d_in[0];
    const float* prev = (const float*)d_in[1];
    const float* Wq   = (const float*)d_in[2];
    const float* bq   = (const float*)d_in[3];
    const float* Wk   = (const float*)d_in[4];
    const float* bk   = (const float*)d_in[5];
    const float* Wc   = (const float*)d_in[6];
    const float* bc   = (const float*)d_in[7];
    const float* W1   = (const float*)d_in[8];
    const float* b1   = (const float*)d_in[9];
    const float* W2   = (const float*)d_in[10];
    const float* b2   = (const float*)d_in[11];
    float* out = (float*)d_out;

    int gemm_smem = (128 * 65 + 128 * 32) * (int)sizeof(float);      // 49664
    int pair_smem = (2 * TSP * HD + HD + 64 * 65) * (int)sizeof(float); // 82688
    cudaFuncSetAttribute(gemm_kernel,
                         cudaFuncAttributeMaxDynamicSharedMemorySize, gemm_smem);
    cudaFuncSetAttribute(pair_kernel,
                         cudaFuncAttributeMaxDynamicSharedMemorySize, pair_smem);

    wfuse_kernel<<<dim3(8, 4, 3), 128>>>(Wq, Wk, W1, emb, Wc, bc, bq, bk, b1);
    gemm_kernel<<<dim3(8, 16, 2), 128, gemm_smem>>>(prev);
    pair_kernel<<<136, 512, pair_smem>>>(W2, b2, out);
}

// round 6
// speedup vs baseline: 1.1504x; 1.1504x over previous
#include <cuda_runtime.h>
#include <cuda_bf16.h>

#define N        1024
#define ED       256
#define HD       128
#define TSP      64      // pair-tile size

// ---------------- scratch (no allocation allowed) ----------------
__device__ float g_WfA[ED * 2 * HD];     // fused-weight partial, k 0..63
__device__ float g_WfB[ED * 2 * HD];     // fused-weight partial, k 64..127
__device__ float g_biasf[2 * HD];        // fused biases (q half includes b1)
__device__ float g_qkA[N * 2 * HD];      // qk partial, e 0..127
__device__ float g_qkB[N * 2 * HD];      // qk partial, e 128..255

// ---------------- kernel A: ctx + fused biases, wide-parallel --------------
// ctx = relu(emb@Wc + bc)
// biasf[h]     = b1[h] + sum_k (bq[k]+ctx[k]) * W1[k][h]
// biasf[128+h] =         sum_k (bk[k]+ctx[k]) * W1[128+k][h]
__global__ void __launch_bounds__(1024)
ctxbias_kernel(const float* __restrict__ emb,
               const float* __restrict__ Wc,
               const float* __restrict__ bc,
               const float* __restrict__ bq,
               const float* __restrict__ bk,
               const float* __restrict__ b1,
               const float* __restrict__ W1) {
    __shared__ float semb[ED];
    __shared__ float part1[8][HD];     // ctx partials
    __shared__ float sqk[2][HD];       // bq+ctx, bk+ctx
    __shared__ float part2[4][256];    // bias partials
    int t = threadIdx.x;
    if (t < ED) semb[t] = emb[t];
    __syncthreads();
    {   // ctx matvec: 8 partial-threads per output h, 32-deep each
        int p = t >> 7;                // 0..7
        int h = t & 127;
        int kb = p * 32;
        const float* wp = Wc + h;
        float s = 0.f;
        #pragma unroll
        for (int k = 0; k < 32; k++)
            s = fmaf(semb[kb + k], wp[(kb + k) * HD], s);
        part1[p][h] = s;
    }
    __syncthreads();
    if (t < HD) {
        float s = bc[t];
        #pragma unroll
        for (int p = 0; p < 8; p++) s += part1[p][t];
        float ctx = fmaxf(s, 0.f);
        sqk[0][t] = bq[t] + ctx;
        sqk[1][t] = bk[t] + ctx;
    }
    __syncthreads();
    {   // bias GEMV: 4 partial-threads per output c, 32-deep each
        int p = t >> 8;                // 0..3
        int c = t & 255;
        int half = c >> 7;             // 0: q-half (W1 top), 1: k-half (W1 bot)
        int col = c & 127;
        int kb = p * 32;
        const float* w1p = W1 + (half * HD + kb) * HD + col;
        const float* v = &sqk[half][kb];
        float s = 0.f;
        #pragma unroll
        for (int k = 0; k < 32; k++)
            s = fmaf(v[k], w1p[k * HD], s);
        part2[p][c] = s;
    }
    __syncthreads();
    if (t < 256) {
        float s = (t < HD) ? b1[t] : 0.f;
        #pragma unroll
        for (int p = 0; p < 4; p++) s += part2[p][t];
        g_biasf[t] = s;
    }
}

// ---------------- kernel B: fused weights Wf = [Wq@W1top | Wk@W1bot] ------
// GEMM 256x256x128, split-K=2. grid (8 n, 4 m, 2 k), 128 threads, 4x4/thread.
__global__ void __launch_bounds__(128)
wfuse_kernel(const float* __restrict__ Wq,
             const float* __restrict__ Wk,
             const float* __restrict__ W1) {
    __shared__ float AsT[64 * 65];   // [k][e], scalar-store transpose, stride 65
    __shared__ float Bs[64][32];     // [k][n]
    int nb = blockIdx.x * 32;
    int e0 = blockIdx.y * 64;
    int k0 = blockIdx.z * 64;
    int half = nb >> 7;              // 0 -> q-cols (Wq/W1top), 1 -> k-cols
    int ncol = nb & 127;
    const float* A = half ? Wk : Wq;
    int t = threadIdx.x, tx = t & 7, ty = t >> 3;

    #pragma unroll
    for (int l = 0; l < 8; l++) {              // A: 64(e) x 64(k), transposed
        int idx = l * 128 + t;
        int e16 = idx & 15, i = idx >> 4;
        float4 v = *(const float4*)&A[(e0 + i) * HD + k0 + 4 * e16];
        AsT[(4 * e16 + 0) * 65 + i] = v.x;
        AsT[(4 * e16 + 1) * 65 + i] = v.y;
        AsT[(4 * e16 + 2) * 65 + i] = v.z;
        AsT[(4 * e16 + 3) * 65 + i] = v.w;
    }
    #pragma unroll
    for (int l = 0; l < 4; l++) {              // B: 64x32 floats
        int idx = l * 128 + t;
        int c4 = idx & 7, row = idx >> 3;
        *(float4*)&Bs[row][4 * c4] =
            *(const float4*)&W1[(half * HD + k0 + row) * HD + ncol + 4 * c4];
    }
    __syncthreads();

    float acc[4][4] = {};
    #pragma unroll 4
    for (int k = 0; k < 64; k++) {
        float a0 = AsT[k * 65 + 4 * ty + 0];
        float a1 = AsT[k * 65 + 4 * ty + 1];
        float a2 = AsT[k * 65 + 4 * ty + 2];
        float a3 = AsT[k * 65 + 4 * ty + 3];
        float4 b = *(const float4*)&Bs[k][4 * tx];
        acc[0][0] = fmaf(a0, b.x, acc[0][0]); acc[0][1] = fmaf(a0, b.y, acc[0][1]);
        acc[0][2] = fmaf(a0, b.z, acc[0][2]); acc[0][3] = fmaf(a0, b.w, acc[0][3]);
        acc[1][0] = fmaf(a1, b.x, acc[1][0]); acc[1][1] = fmaf(a1, b.y, acc[1][1]);
        acc[1][2] = fmaf(a1, b.z, acc[1][2]); acc[1][3] = fmaf(a1, b.w, acc[1][3]);
        acc[2][0] = fmaf(a2, b.x, acc[2][0]); acc[2][1] = fmaf(a2, b.y, acc[2][1]);
        acc[2][2] = fmaf(a2, b.z, acc[2][2]); acc[2][3] = fmaf(a2, b.w, acc[2][3]);
        acc[3][0] = fmaf(a3, b.x, acc[3][0]); acc[3][1] = fmaf(a3, b.y, acc[3][1]);
        acc[3][2] = fmaf(a3, b.z, acc[3][2]); acc[3][3] = fmaf(a3, b.w, acc[3][3]);
    }
    float* outp = blockIdx.z ? g_WfB : g_WfA;
    #pragma unroll
    for (int r = 0; r < 4; r++)
        *(float4*)&outp[(e0 + 4 * ty + r) * 256 + nb + 4 * tx] =
            make_float4(acc[r][0], acc[r][1], acc[r][2], acc[r][3]);
}

// ---------------- kernel C: GEMM qk = prev @ Wf (split-K=2) ----------------
__global__ void __launch_bounds__(128)
gemm_kernel(const float* __restrict__ prev) {
    extern __shared__ float sm[];
    float* AsT = sm;                 // [128(k)][65(m)] scalar-store transpose
    float* Bs  = sm + 128 * 65;      // [128][32]
    int nb = blockIdx.x * 32;
    int i0 = blockIdx.y * 64;
    int k0 = blockIdx.z * 128;
    int t = threadIdx.x, tx = t & 7, ty = t >> 3;

    #pragma unroll
    for (int l = 0; l < 16; l++) {             // A: 64(m) x 128(k), transposed
        int idx = l * 128 + t;
        int e4 = idx & 31, i = idx >> 5;
        float4 v = *(const float4*)&prev[(i0 + i) * ED + k0 + 4 * e4];
        AsT[(4 * e4 + 0) * 65 + i] = v.x;
        AsT[(4 * e4 + 1) * 65 + i] = v.y;
        AsT[(4 * e4 + 2) * 65 + i] = v.z;
        AsT[(4 * e4 + 3) * 65 + i] = v.w;
    }
    #pragma unroll
    for (int l = 0; l < 8; l++) {              // B: 128x32, sum wfuse partials
        int idx = l * 128 + t;
        int c4 = idx & 7, row = idx >> 3;
        int off = (k0 + row) * 256 + nb + 4 * c4;
        float4 a = *(const float4*)&g_WfA[off];
        float4 b = *(const float4*)&g_WfB[off];
        *(float4*)&Bs[row * 32 + 4 * c4] =
            make_float4(a.x + b.x, a.y + b.y, a.z + b.z, a.w + b.w);
    }
    __syncthreads();

    float acc[4][4] = {};
    #pragma unroll 4
    for (int k = 0; k < 128; k++) {
        float a0 = AsT[k * 65 + 4 * ty + 0];
        float a1 = AsT[k * 65 + 4 * ty + 1];
        float a2 = AsT[k * 65 + 4 * ty + 2];
        float a3 = AsT[k * 65 + 4 * ty + 3];
        float4 b = *(const float4*)&Bs[k * 32 + 4 * tx];
        acc[0][0] = fmaf(a0, b.x, acc[0][0]); acc[0][1] = fmaf(a0, b.y, acc[0][1]);
        acc[0][2] = fmaf(a0, b.z, acc[0][2]); acc[0][3] = fmaf(a0, b.w, acc[0][3]);
        acc[1][0] = fmaf(a1, b.x, acc[1][0]); acc[1][1] = fmaf(a1, b.y, acc[1][1]);
        acc[1][2] = fmaf(a1, b.z, acc[1][2]); acc[1][3] = fmaf(a1, b.w, acc[1][3]);
        acc[2][0] = fmaf(a2, b.x, acc[2][0]); acc[2][1] = fmaf(a2, b.y, acc[2][1]);
        acc[2][2] = fmaf(a2, b.z, acc[2][2]); acc[2][3] = fmaf(a2, b.w, acc[2][3]);
        acc[3][0] = fmaf(a3, b.x, acc[3][0]); acc[3][1] = fmaf(a3, b.y, acc[3][1]);
        acc[3][2] = fmaf(a3, b.z, acc[3][2]); acc[3][3] = fmaf(a3, b.w, acc[3][3]);
    }
    float* outp = blockIdx.z ? g_qkB : g_qkA;
    #pragma unroll
    for (int r = 0; r < 4; r++)
        *(float4*)&outp[(i0 + 4 * ty + r) * 256 + nb + 4 * tx] =
            make_float4(acc[r][0], acc[r][1], acc[r][2], acc[r][3]);
}

// ---------------- kernel D: pair scores, 512 threads, h-split --------------
#define PSTEP(ACC, QP, KP, WP)                                        \
    asm("{\n\t"                                                       \
        ".reg .b64 s; .reg .f32 lo, hi;\n\t"                          \
        "add.rn.f32x2 s, %1, %2;\n\t"                                 \
        "mov.b64 {lo, hi}, s;\n\t"                                    \
        "max.f32 lo, lo, 0f00000000;\n\t"                             \
        "max.f32 hi, hi, 0f00000000;\n\t"                             \
        "mov.b64 s, {lo, hi};\n\t"                                    \
        "fma.rn.f32x2 %0, s, %3, %0;\n\t"                             \
        "}" : "+l"(ACC) : "l"(QP), "l"(KP), "l"(WP))

__global__ void __launch_bounds__(512, 1)
pair_kernel(const float* __restrict__ W2,
            const float* __restrict__ b2,
            float* __restrict__ out) {
    extern __shared__ float sm[];
    float* qs  = sm;                   // [64][128] swizzled, bias folded
    float* ks  = sm + TSP * HD;        // [64][128] swizzled, bias folded
    float* w2s = sm + 2 * TSP * HD;    // [128]
    float* red = sm + 2 * TSP * HD + HD;  // [64][65] partial-sum scratch

    // decode 1D block id -> upper-triangular tile (it <= jt), 16x16 tiles
    int rem = blockIdx.x;
    int it = 0;
    #pragma unroll
    for (int r = 0; r < 16; r++) {
        int len = 16 - r;
        if (rem < len) { it = r; break; }
        rem -= len;
    }
    int jt = it + rem;

    int t = threadIdx.x;
    int ibase = it * TSP, jbase = jt * TSP;

    // load tiles: sum split-K partials + fold fused bias; XOR-swizzled rows
    {
        int h4 = t & 31;                       // fixed column group per thread
        float4 bq4 = *(const float4*)&g_biasf[4 * h4];
        float4 bk4 = *(const float4*)&g_biasf[HD + 4 * h4];
        #pragma unroll
        for (int l = 0; l < 4; l++) {
            int i = (t >> 5) + 16 * l;
            int qo = (ibase + i) * 256 + 4 * h4;
            int ko = (jbase + i) * 256 + HD + 4 * h4;
            float4 qa = *(const float4*)&g_qkA[qo];
            float4 qb = *(const float4*)&g_qkB[qo];
            float4 ka = *(const float4*)&g_qkA[ko];
            float4 kb = *(const float4*)&g_qkB[ko];
            float4 qv = make_float4(qa.x + qb.x + bq4.x, qa.y + qb.y + bq4.y,
                                    qa.z + qb.z + bq4.z, qa.w + qb.w + bq4.w);
            float4 kv = make_float4(ka.x + kb.x + bk4.x, ka.y + kb.y + bk4.y,
                                    ka.z + kb.z + bk4.z, ka.w + kb.w + bk4.w);
            int sw = 4 * (h4 ^ ((i >> 2) & 7));
            *(float4*)&qs[i * HD + sw] = qv;
            *(float4*)&ks[i * HD + sw] = kv;
        }
    }
    if (t < HD) w2s[t] = W2[t];
    __syncthreads();

    int hg = t >> 8;                // h-group: 0 -> h4 0..15, 1 -> h4 16..31
    int tt = t & 255;
    int tx = tt & 15, ty = tt >> 4;
    int i0 = ty * 4, j0 = tx * 4;
    int swq = ty & 7, swk = tx & 7;

    unsigned long long acc[4][4];
    #pragma unroll
    for (int a = 0; a < 4; a++)
        #pragma unroll
        for (int b = 0; b < 4; b++)
            acc[a][b] = 0ull;

    int h4beg = hg * 16;
    #pragma unroll 2
    for (int hh = 0; hh < 16; hh++) {
        int h4 = h4beg + hh;
        int hq = 4 * (h4 ^ swq);
        int hk = 4 * (h4 ^ swk);
        ulonglong2 q[4], k[4];
        #pragma unroll
        for (int a = 0; a < 4; a++)
            q[a] = *(const ulonglong2*)&qs[(i0 + a) * HD + hq];
        #pragma unroll
        for (int b = 0; b < 4; b++)
            k[b] = *(const ulonglong2*)&ks[(j0 + b) * HD + hk];
        ulonglong2 w = *(const ulonglong2*)&w2s[4 * h4];
        #pragma unroll
        for (int a = 0; a < 4; a++)
            #pragma unroll
            for (int b = 0; b < 4; b++) {
                PSTEP(acc[a][b], q[a].x, k[b].x, w.x);
                PSTEP(acc[a][b], q[a].y, k[b].y, w.y);
            }
    }

    // reduce packed halves -> scalar partials
    float s[4][4];
    #pragma unroll
    for (int a = 0; a < 4; a++)
        #pragma unroll
        for (int b = 0; b < 4; b++) {
            unsigned long long v = acc[a][b];
            s[a][b] = __int_as_float((unsigned)v) +
                      __int_as_float((unsigned)(v >> 32));
        }

    // h-high half deposits partials in smem scratch
    if (hg) {
        #pragma unroll
        for (int a = 0; a < 4; a++)
            #pragma unroll
            for (int b = 0; b < 4; b++)
                red[(i0 + a) * 65 + j0 + b] = s[a][b];
    }
    __syncthreads();

    if (!hg) {
        float bias = b2[0];
        #pragma unroll
        for (int a = 0; a < 4; a++) {
            int i = ibase + i0 + a;
            int rowoff = i * N - ((i * (i + 1)) >> 1) - i - 1;
            #pragma unroll
            for (int b = 0; b < 4; b++) {
                int j = jbase + j0 + b;
                if (i < j)
                    out[rowoff + j] =
                        s[a][b] + red[(i0 + a) * 65 + j0 + b] + bias;
            }
        }
    }
}

// ---------------- launch ----------------
extern "C" void kernel_launch(void* const* d_in, const int* in_sizes, int n_in,
                              void* d_out, int out_size) {
    const float* emb  = (const float*)d_in[0];
    const float* prev = (const float*)d_in[1];
    const float* Wq   = (const float*)d_in[2];
    const float* bq   = (const float*)d_in[3];
    const float* Wk   = (const float*)d_in[4];
    const float* bk   = (const float*)d_in[5];
    const float* Wc   = (const float*)d_in[6];
    const float* bc   = (const float*)d_in[7];
    const float* W1   = (const float*)d_in[8];
    const float* b1   = (const float*)d_in[9];
    const float* W2   = (const float*)d_in[10];
    const float* b2   = (const float*)d_in[11];
    float* out = (float*)d_out;

    int gemm_smem = (128 * 65 + 128 * 32) * (int)sizeof(float);      // 49664
    int pair_smem = (2 * TSP * HD + HD + 64 * 65) * (int)sizeof(float); // 82688
    cudaFuncSetAttribute(gemm_kernel,
                         cudaFuncAttributeMaxDynamicSharedMemorySize, gemm_smem);
    cudaFuncSetAttribute(pair_kernel,
                         cudaFuncAttributeMaxDynamicSharedMemorySize, pair_smem);

    ctxbias_kernel<<<1, 1024>>>(emb, Wc, bc, bq, bk, b1, W1);
    wfuse_kernel<<<dim3(8, 4, 2), 128>>>(Wq, Wk, W1);
    gemm_kernel<<<dim3(8, 16, 2), 128, gemm_smem>>>(prev);
    pair_kernel<<<136, 512, pair_smem>>>(W2, b2, out);
}